// round 16
// baseline (speedup 1.0000x reference)
#include <cuda_runtime.h>
#include <cstdint>

// LengthRegulator, fixed shapes: B=32, T=512, D=384, ML=4096.
//   K1 (precompute, grid(32,4)): cumsum + searchsorted -> tokpack + mel_pos.
//   K2 (persistent scatter, 608 CTAs, PDL): each CTA loops over tiles with a
//      2-deep smem pipeline: dedup+issue cp.async gathers for tile k+1 while
//      storing tile k (wait_group 1). Hides L2 gather latency behind stores.
// d_out layout: [B*ML*D floats (out)] then [B*ML floats (mel_pos as float)]

#define B_FIXED 32
#define T_FIXED 512
#define D_FIXED 384
#define ML_FIXED 4096
#define FPB 16
#define QV 96                       // float4 per frame row
#define TPB 256
#define K1_SPLIT 4
#define K1_FR (ML_FIXED / K1_SPLIT / T_FIXED)
#define NT ((B_FIXED * ML_FIXED) / FPB)          // 8192 tiles
#define TILES_PER_BATCH (ML_FIXED / FPB)         // 256
#define NCTA 608                                 // persistent grid

__device__ int g_tokpack[B_FIXED * ML_FIXED];    // tok | (valid<<16)

// ---------------- K1: precompute ----------------
__global__ void __launch_bounds__(T_FIXED)
lr_precompute(const int* __restrict__ dur, float* __restrict__ melpos)
{
    __shared__ int cum[T_FIXED];
    __shared__ int woff[16];

    const int b  = blockIdx.x;
    const int sb = blockIdx.y;
    const int t  = threadIdx.x;
    const int lane = t & 31;
    const int w = t >> 5;

    int d = dur[b * T_FIXED + t];
    int v = d;
    #pragma unroll
    for (int off = 1; off < 32; off <<= 1) {
        int n = __shfl_up_sync(0xFFFFFFFFu, v, off);
        if (lane >= off) v += n;
    }
    if (lane == 31) woff[w] = v;
    __syncthreads();
    if (t < 16) {
        int wv = woff[t];
        #pragma unroll
        for (int off = 1; off < 16; off <<= 1) {
            int n = __shfl_up_sync(0x0000FFFFu, wv, off);
            if (t >= off) wv += n;
        }
        woff[t] = wv - woff[t];
    }
    __syncthreads();
    cum[t] = v + woff[w];
    __syncthreads();

    const int total = cum[T_FIXED - 1];
    const int fbase = sb * (ML_FIXED / K1_SPLIT);

    #pragma unroll
    for (int j = 0; j < K1_FR; ++j) {
        const int f = fbase + j * T_FIXED + t;
        int lo = 0, hi = T_FIXED;
        #pragma unroll
        for (int step = 0; step < 10; ++step) {      // interval must reach 0
            if (lo < hi) {
                int mid = (lo + hi) >> 1;
                if (cum[mid] <= f) lo = mid + 1; else hi = mid;
            }
        }
        int tok   = (lo < T_FIXED - 1) ? lo : (T_FIXED - 1);
        int valid = (f < total);
        g_tokpack[b * ML_FIXED + f] = tok | (valid << 16);
        melpos[(size_t)b * ML_FIXED + f] = valid ? (float)(f + 1) : 0.0f;
    }

#if __CUDA_ARCH__ >= 900
    cudaTriggerProgrammaticLaunchCompletion();
#endif
}

// ---------------- K2: persistent double-buffered scatter ----------------
struct TileMeta { int uniq[FPB]; int slotv[FPB]; int n; };

__device__ __forceinline__ void dedup_tile(int g, TileMeta* m, int t)
{
    // warp 0 only. valid frames are a prefix; tok is monotone within a tile.
    int tp = (t < FPB) ? g_tokpack[g * FPB + t] : 0;   // tiles are contiguous in tokpack
    int tok   = tp & 0xFFFF;
    int valid = tp >> 16;
    int ptok  = __shfl_up_sync(0xFFFFFFFFu, tok, 1);
    bool isnew = valid && ((t == 0) || tok != ptok);
    unsigned mm = __ballot_sync(0xFFFFFFFFu, isnew);
    int slot = __popc(mm & ((2u << t) - 1u)) - 1;
    if (isnew) m->uniq[slot] = tok;
    if (t < FPB) m->slotv[t] = (slot & 0xFFFF) | (valid << 16);
    if (t == 0) m->n = __popc(mm);
}

__device__ __forceinline__ void issue_gather(const float4* __restrict__ x4all,
                                             int g, const TileMeta* m,
                                             float4* tilebuf, int t)
{
    const int b = g / TILES_PER_BATCH;
    const float4* __restrict__ x4 = x4all + (size_t)b * T_FIXED * QV;
    const int n = m->n;
    for (int i = t; i < n * QV; i += TPB) {
        int r = i / QV;
        int q = i - r * QV;
        const float4* src = &x4[(size_t)m->uniq[r] * QV + q];
        uint32_t dst = (uint32_t)__cvta_generic_to_shared(&tilebuf[i]);
        asm volatile("cp.async.cg.shared.global [%0], [%1], 16;"
                     :: "r"(dst), "l"(src) : "memory");
    }
    asm volatile("cp.async.commit_group;" ::: "memory");
}

__device__ __forceinline__ void store_tile(float* __restrict__ out,
                                           int g, const TileMeta* m,
                                           const float4* tilebuf, int t)
{
    float4* __restrict__ o4 = (float4*)out + (size_t)g * FPB * QV;  // tiles contiguous
    const float4 zero = make_float4(0.f, 0.f, 0.f, 0.f);
    #pragma unroll
    for (int j = 0; j < (FPB * QV) / TPB; ++j) {
        const int i  = j * TPB + t;
        const int fr = i / QV;
        const int q  = i - fr * QV;
        const int sv = m->slotv[fr];
        float4 val = (sv >> 16) ? tilebuf[(sv & 0xFFFF) * QV + q] : zero;
        __stcs(&o4[(size_t)fr * QV + q], val);
    }
}

__global__ void __launch_bounds__(TPB)
lr_scatter(const float* __restrict__ x, float* __restrict__ out)
{
    __shared__ __align__(16) float4 tile[2][FPB * QV];   // 2 x 24 KB
    __shared__ TileMeta meta[2];

    const int t = threadIdx.x;
    const float4* __restrict__ x4all = (const float4*)x;

#if __CUDA_ARCH__ >= 900
    cudaGridDependencySynchronize();      // wait for K1's g_tokpack
#endif

    int g = blockIdx.x;
    if (g >= NT) return;

    // prologue: tile g into buffer 0
    if (t < 32) dedup_tile(g, &meta[0], t);
    __syncthreads();
    issue_gather(x4all, g, &meta[0], tile[0], t);

    int cur = 0;
    while (true) {
        const int gn = g + NCTA;
        const bool has_next = (gn < NT);

        if (has_next && t < 32) dedup_tile(gn, &meta[cur ^ 1], t);
        __syncthreads();                               // dedup visible
        if (has_next) issue_gather(x4all, gn, &meta[cur ^ 1], tile[cur ^ 1], t);

        if (has_next)
            asm volatile("cp.async.wait_group 1;" ::: "memory");
        else
            asm volatile("cp.async.wait_group 0;" ::: "memory");
        __syncthreads();                               // gathered data visible

        store_tile(out, g, &meta[cur], tile[cur], t);

        if (!has_next) break;
        g = gn;
        cur ^= 1;
        __syncthreads();    // protect meta/tile[cur] reuse vs. slow warps
    }
}

extern "C" void kernel_launch(void* const* d_in, const int* in_sizes, int n_in,
                              void* d_out, int out_size)
{
    const float* x   = (const float*)d_in[0];
    const int*   dur = (const int*)d_in[1];

    float* out    = (float*)d_out;
    float* melpos = out + (size_t)B_FIXED * ML_FIXED * D_FIXED;

    lr_precompute<<<dim3(B_FIXED, K1_SPLIT), T_FIXED>>>(dur, melpos);

    cudaLaunchConfig_t cfg = {};
    cfg.gridDim  = dim3(NCTA);
    cfg.blockDim = dim3(TPB);
    cfg.dynamicSmemBytes = 0;
    cfg.stream = 0;
    cudaLaunchAttribute attr[1];
    attr[0].id = cudaLaunchAttributeProgrammaticStreamSerialization;
    attr[0].val.programmaticStreamSerializationAllowed = 1;
    cfg.attrs = attr;
    cfg.numAttrs = 1;
    cudaLaunchKernelEx(&cfg, lr_scatter, x, out);
}